// round 4
// baseline (speedup 1.0000x reference)
#include <cuda_runtime.h>
#include <cuda_bf16.h>
#include <cstdint>

#define NN 50000
#define EE 400000
#define FF 256
#define HH 512
#define CC 3
#define NPAD 50048              // 391 * 128

// ---------------- device scratch ----------------
__device__ float g_X[(size_t)NPAD * HH];          // fp32 activations
__device__ __nv_bfloat16 g_Ah[(size_t)NPAD * HH]; // agg output hi
__device__ __nv_bfloat16 g_Am[(size_t)NPAD * HH]; // agg output mid
__device__ __nv_bfloat16 g_Wh[(size_t)13 * HH * HH];  // transposed [n][k]
__device__ __nv_bfloat16 g_Wm[(size_t)13 * HH * HH];
__device__ float g_S[(size_t)NN * CC];
__device__ float g_dinv[NN];
__device__ float g_coef[EE + NN];   // CSR coefs incl. self loops
__device__ int   g_col[EE + NN];
__device__ int   g_srcA[EE];
__device__ int   g_dstA[EE];
__device__ int   g_cnt[NN];
__device__ int   g_fill[NN];
__device__ int   g_rowptr[NN + 1];
__device__ unsigned g_is32;

// ---------------- preprocessing ----------------
__global__ void detect_kernel(const unsigned* __restrict__ w) {
    unsigned local = 0;
    for (int i = blockIdx.x * blockDim.x + threadIdx.x; i < EE;
         i += gridDim.x * blockDim.x)
        local |= w[2 * i + 1];
    #pragma unroll
    for (int off = 16; off; off >>= 1)
        local |= __shfl_xor_sync(0xffffffffu, local, off);
    if ((threadIdx.x & 31) == 0 && local) atomicOr(&g_is32, 1u);
}

__global__ void convert_count_kernel(const void* __restrict__ ei) {
    int e = blockIdx.x * blockDim.x + threadIdx.x;
    if (e >= EE) return;
    int s, d;
    if (g_is32) {
        const int* p = (const int*)ei;
        s = p[e]; d = p[EE + e];
    } else {
        const long long* p = (const long long*)ei;
        s = (int)p[e]; d = (int)p[EE + e];
    }
    g_srcA[e] = s; g_dstA[e] = d;
    atomicAdd(&g_cnt[d], 1);
}

// single block: exclusive scan of (cnt+1), dinv, self-loop CSR entries
__global__ void scan_kernel() {
    __shared__ int s[1024];
    const int T = 1024;
    int tid = threadIdx.x;
    int chunk = (NN + T - 1) / T;
    int beg = tid * chunk;
    int end = min(beg + chunk, NN);
    int sum = 0;
    for (int i = beg; i < end; i++) sum += g_cnt[i] + 1;
    s[tid] = sum;
    __syncthreads();
    for (int off = 1; off < T; off <<= 1) {
        int v = (tid >= off) ? s[tid - off] : 0;
        __syncthreads();
        s[tid] += v;
        __syncthreads();
    }
    int run = (tid > 0) ? s[tid - 1] : 0;
    for (int i = beg; i < end; i++) {
        int c = g_cnt[i];
        float di = rsqrtf((float)c + 1.0f);
        g_rowptr[i] = run;
        g_dinv[i] = di;
        g_col[run + c] = i;          // self-loop in last slot
        g_coef[run + c] = di * di;
        run += c + 1;
    }
    if (tid == T - 1) g_rowptr[NN] = run;
}

__global__ void fill_kernel() {
    int e = blockIdx.x * blockDim.x + threadIdx.x;
    if (e >= EE) return;
    int d = g_dstA[e], s = g_srcA[e];
    int pos = g_rowptr[d] + atomicAdd(&g_fill[d], 1);
    g_col[pos]  = s;
    g_coef[pos] = g_dinv[s] * g_dinv[d];
}

// ---------------- weight transpose + bf16 hi/mid split ----------------
__global__ void wsplit_kernel(const float* __restrict__ W0,
                              const float* __restrict__ Wr) {
    int L = blockIdx.y;
    int n = blockIdx.x;
    int K = (L == 0) ? FF : HH;
    const float* W = (L == 0) ? W0 : (Wr + (size_t)(L - 1) * HH * HH);
    size_t slot = (size_t)L * HH * HH;
    for (int k = threadIdx.x; k < K; k += blockDim.x) {
        float x = W[(size_t)k * HH + n];
        __nv_bfloat16 h = __float2bfloat16_rn(x);
        float r = x - __bfloat162float(h);
        g_Wh[slot + (size_t)n * K + k] = h;
        g_Wm[slot + (size_t)n * K + k] = __float2bfloat16_rn(r);
    }
}

// ---------------- aggregation: bf16 hi/mid split output ----------------
template <int W4>
__global__ void agg_kernel(const float* __restrict__ X,
                           __nv_bfloat16* __restrict__ Th,
                           __nv_bfloat16* __restrict__ Tm, int sA) {
    int node = blockIdx.x;
    int t = threadIdx.x;
    const float4* Xv = (const float4*)X;
    float4 acc = make_float4(0.f, 0.f, 0.f, 0.f);
    int beg = g_rowptr[node], end = g_rowptr[node + 1];
    for (int e = beg; e < end; e++) {
        int s = g_col[e];
        float cf = g_coef[e];
        float4 v = Xv[(size_t)s * W4 + t];
        acc.x += cf * v.x; acc.y += cf * v.y;
        acc.z += cf * v.z; acc.w += cf * v.w;
    }
    float vals[4] = {acc.x, acc.y, acc.z, acc.w};
    unsigned hb[4], mb[4];
    #pragma unroll
    for (int i = 0; i < 4; i++) {
        __nv_bfloat16 h = __float2bfloat16_rn(vals[i]);
        float r = vals[i] - __bfloat162float(h);
        __nv_bfloat16 m = __float2bfloat16_rn(r);
        hb[i] = (unsigned)__bfloat16_as_ushort(h);
        mb[i] = (unsigned)__bfloat16_as_ushort(m);
    }
    uint2 ph, pm;
    ph.x = hb[0] | (hb[1] << 16); ph.y = hb[2] | (hb[3] << 16);
    pm.x = mb[0] | (mb[1] << 16); pm.y = mb[2] | (mb[3] << 16);
    size_t off = (size_t)node * sA + 4 * t;
    *(uint2*)(Th + off) = ph;
    *(uint2*)(Tm + off) = pm;
}

// ---------------- HMMA bf16x3 GEMM, 128x256 tile, 512 thr, 3-stage ----------------
// smem stage (48KB): Ah[128][64B] | Am | Bh[256][64B] | Bm, 64B pitch,
// 16B-block XOR swizzle: blk_phys = blk ^ ((row>>1)&3).
#define SSTG   49152
#define GSMEM3 (3 * SSTG)

#define MMA_B16(cc, A0, A1, A2, A3, B0, B1)                                   \
    asm volatile(                                                             \
        "mma.sync.aligned.m16n8k16.row.col.f32.bf16.bf16.f32 "                \
        "{%0,%1,%2,%3}, {%4,%5,%6,%7}, {%8,%9}, {%0,%1,%2,%3};"               \
        : "+f"(cc[0]), "+f"(cc[1]), "+f"(cc[2]), "+f"(cc[3])                  \
        : "r"(A0), "r"(A1), "r"(A2), "r"(A3), "r"(B0), "r"(B1))

__global__ void __launch_bounds__(512, 1) gemm_mma_kernel(
    const __nv_bfloat16* __restrict__ Ah, const __nv_bfloat16* __restrict__ Am,
    const __nv_bfloat16* __restrict__ Wh, const __nv_bfloat16* __restrict__ Wm,
    const float* __restrict__ bias, float* __restrict__ Xout,
    int M, int K, int sA) {
    extern __shared__ char smb[];
    uint32_t sbase;
    asm("{ .reg .u64 t; cvta.to.shared.u64 t, %1; cvt.u32.u64 %0, t; }"
        : "=r"(sbase) : "l"(smb));

    const int tid = threadIdx.x;
    const int lane = tid & 31, wid = tid >> 5;
    const int g = lane >> 2, t4 = lane & 3;
    const int warpM = wid & 1, warpN = wid >> 1;        // 2 x 8 warps
    const int mBase = blockIdx.x * 128, nBase = blockIdx.y * 256;
    const int nChunks = K >> 5;

    // staging geometry (fixed per thread)
    const int aRow = tid >> 2, aC16 = tid & 3;
    const uint32_t aDst = aRow * 64 + ((aC16 ^ ((aRow >> 1) & 3)) << 4);
    const int aSz = (mBase + aRow < M) ? 16 : 0;
    const long long aOffB = (long long)(mBase + aRow) * sA + aC16 * 8;
    const int bRow0 = tid >> 2, bRow1 = (tid + 512) >> 2;
    const uint32_t bDst0 = 16384 + bRow0 * 64 + ((aC16 ^ ((bRow0 >> 1) & 3)) << 4);
    const uint32_t bDst1 = 16384 + bRow1 * 64 + ((aC16 ^ ((bRow1 >> 1) & 3)) << 4);
    const long long bOff0 = (long long)(nBase + bRow0) * K + aC16 * 8;
    const long long bOff1 = (long long)(nBase + bRow1) * K + aC16 * 8;

    float acc[4][4][4];
    #pragma unroll
    for (int i = 0; i < 4; i++)
        #pragma unroll
        for (int j = 0; j < 4; j++)
            #pragma unroll
            for (int v = 0; v < 4; v++) acc[i][j][v] = 0.f;

    #define STAGE_LOAD(s, chunk) do {                                          \
        int k0 = (chunk) * 32;                                                  \
        uint32_t st = sbase + (s) * SSTG;                                       \
        asm volatile("cp.async.cg.shared.global [%0], [%1], 16, %2;"            \
            :: "r"(st + aDst), "l"(Ah + aOffB + k0), "r"(aSz));                  \
        asm volatile("cp.async.cg.shared.global [%0], [%1], 16, %2;"            \
            :: "r"(st + aDst + 8192), "l"(Am + aOffB + k0), "r"(aSz));           \
        asm volatile("cp.async.cg.shared.global [%0], [%1], 16;"                \
            :: "r"(st + bDst0), "l"(Wh + bOff0 + k0));                           \
        asm volatile("cp.async.cg.shared.global [%0], [%1], 16;"                \
            :: "r"(st + bDst0 + 16384), "l"(Wm + bOff0 + k0));                   \
        asm volatile("cp.async.cg.shared.global [%0], [%1], 16;"                \
            :: "r"(st + bDst1), "l"(Wh + bOff1 + k0));                           \
        asm volatile("cp.async.cg.shared.global [%0], [%1], 16;"                \
            :: "r"(st + bDst1 + 16384), "l"(Wm + bOff1 + k0));                   \
        asm volatile("cp.async.commit_group;");                                 \
    } while (0)

    STAGE_LOAD(0, 0);
    STAGE_LOAD(1, 1);

    int sIdx = 0;
    for (int c = 0; c < nChunks; c++) {
        if (c + 1 < nChunks) asm volatile("cp.async.wait_group 1;");
        else                 asm volatile("cp.async.wait_group 0;");
        __syncthreads();
        if (c + 2 < nChunks) {
            int ns = sIdx + 2; if (ns >= 3) ns -= 3;
            STAGE_LOAD(ns, c + 2);
        }
        const char* stg = smb + sIdx * SSTG;
        #pragma unroll
        for (int kk = 0; kk < 32; kk += 16) {
            const int blk = kk >> 3;
            uint32_t bh[4][2], bm[4][2];
            #pragma unroll
            for (int j = 0; j < 4; j++) {
                int r = warpN * 32 + j * 8 + g;
                int cr = (r >> 1) & 3;
                const char* bp = stg + 16384 + r * 64 + 4 * t4;
                uint32_t o0 = (uint32_t)((blk ^ cr) << 4);
                uint32_t o1 = (uint32_t)(((blk + 1) ^ cr) << 4);
                bh[j][0] = *(const uint32_t*)(bp + o0);
                bh[j][1] = *(const uint32_t*)(bp + o1);
                bm[j][0] = *(const uint32_t*)(bp + 16384 + o0);
                bm[j][1] = *(const uint32_t*)(bp + 16384 + o1);
            }
            #pragma unroll
            for (int i = 0; i < 4; i++) {
                int r0 = warpM * 64 + i * 16 + g;
                int r1 = r0 + 8;
                int c0 = (r0 >> 1) & 3, c1 = (r1 >> 1) & 3;
                const char* ap0 = stg + r0 * 64 + 4 * t4;
                const char* ap1 = stg + r1 * 64 + 4 * t4;
                uint32_t o00 = (uint32_t)((blk ^ c0) << 4);
                uint32_t o01 = (uint32_t)(((blk + 1) ^ c0) << 4);
                uint32_t o10 = (uint32_t)((blk ^ c1) << 4);
                uint32_t o11 = (uint32_t)(((blk + 1) ^ c1) << 4);
                uint32_t ah0 = *(const uint32_t*)(ap0 + o00);
                uint32_t ah1 = *(const uint32_t*)(ap1 + o10);
                uint32_t ah2 = *(const uint32_t*)(ap0 + o01);
                uint32_t ah3 = *(const uint32_t*)(ap1 + o11);
                uint32_t am0 = *(const uint32_t*)(ap0 + 8192 + o00);
                uint32_t am1 = *(const uint32_t*)(ap1 + 8192 + o10);
                uint32_t am2 = *(const uint32_t*)(ap0 + 8192 + o01);
                uint32_t am3 = *(const uint32_t*)(ap1 + 8192 + o11);
                #pragma unroll
                for (int j = 0; j < 4; j++) {
                    MMA_B16(acc[i][j], ah0, ah1, ah2, ah3, bh[j][0], bh[j][1]);
                    MMA_B16(acc[i][j], am0, am1, am2, am3, bh[j][0], bh[j][1]);
                    MMA_B16(acc[i][j], ah0, ah1, ah2, ah3, bm[j][0], bm[j][1]);
                }
            }
        }
        sIdx++; if (sIdx >= 3) sIdx -= 3;
    }

    // epilogue: bias + relu, fp32 out (row stride HH)
    #pragma unroll
    for (int j = 0; j < 4; j++) {
        int col = nBase + warpN * 32 + j * 8 + 2 * t4;
        float bv0 = __ldg(&bias[col]), bv1 = __ldg(&bias[col + 1]);
        #pragma unroll
        for (int i = 0; i < 4; i++) {
            int r0 = mBase + warpM * 64 + i * 16 + g;
            if (r0 < M) {
                float2 v0 = make_float2(fmaxf(acc[i][j][0] + bv0, 0.f),
                                        fmaxf(acc[i][j][1] + bv1, 0.f));
                *(float2*)(Xout + (size_t)r0 * HH + col) = v0;
            }
            int r1 = r0 + 8;
            if (r1 < M) {
                float2 v1 = make_float2(fmaxf(acc[i][j][2] + bv0, 0.f),
                                        fmaxf(acc[i][j][3] + bv1, 0.f));
                *(float2*)(Xout + (size_t)r1 * HH + col) = v1;
            }
        }
    }
}

// ---------------- final small GEMM: S[N,3] = X[N,512] @ W1[512,3] ----------------
__global__ void gemm_small_kernel(const float* __restrict__ X,
                                  const float* __restrict__ W1,
                                  float* __restrict__ S) {
    int row = blockIdx.x * (blockDim.x / 32) + (threadIdx.x >> 5);
    int lane = threadIdx.x & 31;
    if (row >= NN) return;
    float a0 = 0.f, a1 = 0.f, a2 = 0.f;
    const float* xr = X + (size_t)row * HH;
    for (int k = lane; k < HH; k += 32) {
        float xv = xr[k];
        a0 += xv * W1[k * 3 + 0];
        a1 += xv * W1[k * 3 + 1];
        a2 += xv * W1[k * 3 + 2];
    }
    #pragma unroll
    for (int off = 16; off; off >>= 1) {
        a0 += __shfl_down_sync(0xffffffffu, a0, off);
        a1 += __shfl_down_sync(0xffffffffu, a1, off);
        a2 += __shfl_down_sync(0xffffffffu, a2, off);
    }
    if (lane == 0) {
        S[row * 3 + 0] = a0;
        S[row * 3 + 1] = a1;
        S[row * 3 + 2] = a2;
    }
}

__global__ void agg_final_kernel(const float* __restrict__ S,
                                 const float* __restrict__ b1,
                                 float* __restrict__ out) {
    int i = blockIdx.x * blockDim.x + threadIdx.x;
    if (i >= NN) return;
    float a0 = 0.f, a1 = 0.f, a2 = 0.f;
    int beg = g_rowptr[i], end = g_rowptr[i + 1];
    for (int e = beg; e < end; e++) {
        int s = g_col[e];
        float cf = g_coef[e];
        a0 += cf * S[s * 3 + 0];
        a1 += cf * S[s * 3 + 1];
        a2 += cf * S[s * 3 + 2];
    }
    out[i * 3 + 0] = a0 + b1[0];
    out[i * 3 + 1] = a1 + b1[1];
    out[i * 3 + 2] = a2 + b1[2];
}

// ---------------- host orchestration ----------------
extern "C" void kernel_launch(void* const* d_in, const int* in_sizes, int n_in,
                              void* d_out, int out_size) {
    const float* x  = (const float*)d_in[0];
    const void*  ei = d_in[1];
    const float* W0 = (const float*)d_in[2];
    const float* b0 = (const float*)d_in[3];
    const float* Wr = (const float*)d_in[4];
    const float* br = (const float*)d_in[5];
    const float* W1 = (const float*)d_in[6];
    const float* b1 = (const float*)d_in[7];
    float* out  = (float*)d_out;
    float* outX = out + (size_t)NN * CC;

    float *gX, *gS;
    __nv_bfloat16 *gAh, *gAm, *gWh, *gWm;
    int *gCnt, *gFill;
    unsigned* gIs32;
    cudaGetSymbolAddress((void**)&gX,  g_X);
    cudaGetSymbolAddress((void**)&gS,  g_S);
    cudaGetSymbolAddress((void**)&gAh, g_Ah);
    cudaGetSymbolAddress((void**)&gAm, g_Am);
    cudaGetSymbolAddress((void**)&gWh, g_Wh);
    cudaGetSymbolAddress((void**)&gWm, g_Wm);
    cudaGetSymbolAddress((void**)&gCnt, g_cnt);
    cudaGetSymbolAddress((void**)&gFill, g_fill);
    cudaGetSymbolAddress((void**)&gIs32, g_is32);

    cudaFuncSetAttribute(gemm_mma_kernel,
                         cudaFuncAttributeMaxDynamicSharedMemorySize, GSMEM3);

    // preprocessing: CSR (with self-loops) + normalization + weight split
    cudaMemsetAsync(gCnt, 0, NN * sizeof(int));
    cudaMemsetAsync(gFill, 0, NN * sizeof(int));
    cudaMemsetAsync(gIs32, 0, sizeof(unsigned));
    detect_kernel<<<256, 256>>>((const unsigned*)ei);
    convert_count_kernel<<<(EE + 255) / 256, 256>>>(ei);
    scan_kernel<<<1, 1024>>>();
    fill_kernel<<<(EE + 255) / 256, 256>>>();
    wsplit_kernel<<<dim3(HH, 13), 256>>>(W0, Wr);

    dim3 gg(NPAD / 128, 2);

    // layer 0: agg on F=256 (split output), then HMMA GEMM K=256
    agg_kernel<FF / 4><<<NN, FF / 4>>>(x, gAh, gAm, FF);
    gemm_mma_kernel<<<gg, 512, GSMEM3>>>(gAh, gAm, gWh, gWm, b0, gX,
                                         NN, FF, FF);

    // 12 residual-block convs: relu(A x W + b)
    for (int L = 1; L <= 12; L++) {
        agg_kernel<HH / 4><<<NN, HH / 4>>>(gX, gAh, gAm, HH);
        float* dst = (L == 12) ? outX : gX;
        gemm_mma_kernel<<<gg, 512, GSMEM3>>>(
            gAh, gAm,
            gWh + (size_t)L * HH * HH, gWm + (size_t)L * HH * HH,
            br + (size_t)(L - 1) * HH, dst, NN, HH, HH);
    }

    // final conv: GEMM first (H->3), then aggregate on 3 cols + bias
    gemm_small_kernel<<<(NN + 7) / 8, 256>>>(outX, W1, gS);
    agg_final_kernel<<<(NN + 255) / 256, 256>>>(gS, b1, out);
}